// round 16
// baseline (speedup 1.0000x reference)
#include <cuda_runtime.h>
#include <cuda_fp16.h>
#include <cstdint>

#define BB  2
#define CC  256
#define NN  2304
#define HH  8
#define DHH 64
#define OO  512
#define NKP 2368          // 2304 tokens + null@2304 + 63 pad = 37*64
#define NJ  64
#define NBLK (NKP/NJ)     // 37
#define MT  128
#define NIT (NN/MT)       // 18
#define KP3 768           // 3*256
#define KO3 1536          // 3*512

#define C2F     0.0325213903f    // (0.125*log2e)^2
#define TWO_C2F 0.0650427806f

// ---- scratch (device globals; no allocation allowed) ----
__device__ __align__(16) __half g_normsp[BB*NN*KP3];   // B for proj: (xh,xh,xl) triples, n-major
__device__ __align__(16) __half g_wqk3[OO*KP3];        // A: (wh,wl,wh) triples
__device__ __align__(16) __half g_wv3[OO*KP3];
__device__ __align__(16) __half g_wo3[CC*KO3];
__device__ __align__(16) __half g_kh[BB*HH*NKP*DHH];   // keys fp16 (bh, n, d); null@2304
__device__ __align__(16) __half g_vh[BB*HH*DHH*NKP];   // V fp16 (bh, d, n)
__device__ float g_k2[BB*HH*NKP];                      // C2 * |k_n|^2 of ROUNDED keys; big on pads
__device__ __align__(16) __half g_attsp[BB*NN*KO3];    // B for out: (oh,oh,ol) triples
__device__ float g_Opart[2*16*DHH*NN];                 // split-j partial O (jh, bh, d, i)
__device__ float g_dpart[2*16*NN];                     // split-j partial den (jh, bh, i)
__device__ unsigned int g_flag[NIT*16];                // split-j semaphores (reset in prep)

static __device__ __forceinline__ uint32_t s2u(const void* p){
    uint32_t a;
    asm("{ .reg .u64 t; cvta.to.shared.u64 t, %1; cvt.u32.u64 %0, t; }" : "=r"(a) : "l"(p));
    return a;
}
__device__ __forceinline__ void ldsm4(uint32_t* r, uint32_t addr){
    asm volatile("ldmatrix.sync.aligned.m8n8.x4.shared.b16 {%0,%1,%2,%3}, [%4];"
        : "=r"(r[0]), "=r"(r[1]), "=r"(r[2]), "=r"(r[3]) : "r"(addr));
}
__device__ __forceinline__ void mma16816h(float* c, const uint32_t* a, uint32_t b0, uint32_t b1){
    asm volatile("mma.sync.aligned.m16n8k16.row.col.f32.f16.f16.f32 "
        "{%0,%1,%2,%3}, {%4,%5,%6,%7}, {%8,%9}, {%0,%1,%2,%3};"
        : "+f"(c[0]), "+f"(c[1]), "+f"(c[2]), "+f"(c[3])
        : "r"(a[0]), "r"(a[1]), "r"(a[2]), "r"(a[3]), "r"(b0), "r"(b1));
}
__device__ __forceinline__ uint32_t pack_h2(float x, float y){
    __half2 t = __floats2half2_rn(x, y);
    return *reinterpret_cast<uint32_t*>(&t);
}
__device__ __forceinline__ uint32_t h2ex2(uint32_t x){
    uint32_t r; asm("ex2.approx.f16x2 %0, %1;" : "=r"(r) : "r"(x)); return r;
}
__device__ __forceinline__ float fsqrt(float x){
    float r; asm("sqrt.approx.f32 %0, %1;" : "=f"(r) : "f"(x)); return r;
}
__device__ __forceinline__ unsigned short hfb(float x){
    __half h = __float2half_rn(x);
    return *reinterpret_cast<unsigned short*>(&h);
}
__device__ __forceinline__ float hff(unsigned short u){
    __half h = *reinterpret_cast<__half*>(&u);
    return __half2float(h);
}
__device__ __forceinline__ void cp16(uint32_t d, const void* s){
    asm volatile("cp.async.cg.shared.global [%0], [%1], 16;" :: "r"(d), "l"(s));
}
#define CP_COMMIT() asm volatile("cp.async.commit_group;" ::: "memory")
#define CP_WAIT1()  asm volatile("cp.async.wait_group 1;" ::: "memory")
#define CP_WAIT0()  asm volatile("cp.async.wait_group 0;" ::: "memory")

// ===================== fused RMSNorm + split + transpose =====================
__global__ __launch_bounds__(256, 2) void rms_fused_kernel(const float* __restrict__ fmap,
                                                           const float* __restrict__ gamma) {
    __shared__ float ts[256][33];
    __shared__ float gs[256];
    __shared__ float part[8][32];
    __shared__ float sc[32];
    int b  = blockIdx.x / 72;
    int n0 = (blockIdx.x % 72) * 32;
    int tid = threadIdx.x;
    gs[tid] = gamma[tid];
    #pragma unroll
    for (int e = tid; e < 8192; e += 256) {
        int cc = e >> 5, nn = e & 31;
        ts[cc][nn] = fmap[((size_t)b*CC + cc)*NN + n0 + nn];
    }
    __syncthreads();
    {
        int w = tid >> 5, l = tid & 31;
        float s = 0.f;
        #pragma unroll
        for (int r = 0; r < 32; r++) { float v = ts[w*32 + r][l]; s += v*v; }
        part[w][l] = s;
    }
    __syncthreads();
    if (tid < 32) {
        float t = 0.f;
        #pragma unroll
        for (int i = 0; i < 8; i++) t += part[i][tid];
        sc[tid] = 16.0f / fmaxf(sqrtf(t), 1e-12f);
    }
    __syncthreads();
    int nn = tid >> 3, cseg = (tid & 7)*32;
    float scv = sc[nn];
    char* rowp = (char*)g_normsp + (size_t)(b*NN + n0 + nn)*(KP3*2) + 6*cseg;
    #pragma unroll
    for (int b8 = 0; b8 < 4; b8++) {
        uint32_t u[12];
        #pragma unroll
        for (int pr = 0; pr < 4; pr++) {
            int c = cseg + b8*8 + pr*2;
            float x0 = ts[c][nn]*scv*gs[c];
            float x1 = ts[c+1][nn]*scv*gs[c+1];
            unsigned short h0 = hfb(x0), l0 = hfb(x0 - hff(h0));
            unsigned short h1 = hfb(x1), l1 = hfb(x1 - hff(h1));
            u[pr*3+0] = (uint32_t)h0 | ((uint32_t)h0 << 16);
            u[pr*3+1] = (uint32_t)l0 | ((uint32_t)h1 << 16);
            u[pr*3+2] = (uint32_t)h1 | ((uint32_t)l1 << 16);
        }
        uint4* wp = (uint4*)(rowp + b8*48);
        wp[0] = ((uint4*)u)[0]; wp[1] = ((uint4*)u)[1]; wp[2] = ((uint4*)u)[2];
    }
}

// ===================== weight split + null/pad fill + flag reset (merged) =====================
__global__ __launch_bounds__(256) void prep_kernel(const float* __restrict__ wqk,
                                                   const float* __restrict__ wv,
                                                   const float* __restrict__ wout,
                                                   const float* __restrict__ null_kv) {
    int bid = blockIdx.x;
    if (bid >= 1536 && bid < 1538) {
        int fi = (bid - 1536)*256 + threadIdx.x;
        if (fi < NIT*16) g_flag[fi] = 0;
    }
    if (bid < 1536) {
        int idx = bid*256 + threadIdx.x;   // 393216
        float w;
        unsigned short* d;
        if (idx < 131072)      { w = wqk[idx];           d = (unsigned short*)g_wqk3 + 3*(size_t)idx; }
        else if (idx < 262144) { w = wv[idx - 131072];   d = (unsigned short*)g_wv3  + 3*(size_t)(idx - 131072); }
        else                   { w = wout[idx - 262144]; d = (unsigned short*)g_wo3  + 3*(size_t)(idx - 262144); }
        unsigned short h = hfb(w);
        unsigned short l = hfb(w - hff(h));
        d[0] = h; d[1] = l; d[2] = h;
    } else {
        int tid = (bid - 1536)*256 + threadIdx.x;   // 65536
        int slot  = tid & 63;
        int rowid = tid >> 6;        // bh*64 + d
        int d  = rowid & 63;
        int bh = rowid >> 6;
        int h  = bh & 7;
        if (slot == 0) {
            float kv = null_kv[h*DHH + d];
            float vv = null_kv[HH*DHH + h*DHH + d];
            ((unsigned short*)g_kh)[((size_t)bh*NKP + NN)*DHH + d] = hfb(kv);
            ((unsigned short*)g_vh)[((size_t)bh*DHH + d)*NKP + NN] = hfb(vv);
            if (d == 0) {
                float s = 0.f;
                #pragma unroll
                for (int t = 0; t < 64; t++) { float x = hff(hfb(null_kv[h*DHH + t])); s += x*x; }
                g_k2[(size_t)bh*NKP + NN] = s * C2F;
            }
        } else {
            int n = NN + slot;   // 2305..2367 pads
            ((unsigned short*)g_kh)[((size_t)bh*NKP + n)*DHH + d] = 0;
            ((unsigned short*)g_vh)[((size_t)bh*DHH + d)*NKP + n] = 0;
            if (d == 0) g_k2[(size_t)bh*NKP + n] = 1e9f;
        }
    }
}

// ===================== projection GEMM (triple-fp16 mma, K-split warps, 32-row tiles) =====================
__global__ __launch_bounds__(256, 2) void proj_mma_kernel() {
    __shared__ __align__(1024) unsigned char sb[49152];
    const int tid = threadIdx.x, lane = tid & 31, warp = tid >> 5;
    const int b = blockIdx.z >> 1, mat = blockIdx.z & 1;
    const int h = blockIdx.y, n0 = blockIdx.x * 128;
    const int bh = b*HH + h;
    const uint32_t smem = s2u(sb);
    const char* Wb = (const char*)(mat ? g_wv3 : g_wqk3) + (size_t)h*64*(KP3*2);
    const char* Xb = (const char*)g_normsp + (size_t)(b*NN + n0)*(KP3*2);
    const int wn = warp & 1, wm = (warp >> 1) & 1, wk = warp >> 2;
    const int qo = ((lane>>3)&1)*8 + (lane&7), qsel = ((lane>>4)&1)*8, aswz = (qo&7)<<4;
    const int jo = ((lane>>4)&1)*8 + (lane&7), dsel = ((lane>>3)&1)*8, jswz = (jo&7)<<4;
    float C0[8][4] = {}, C1[8][4] = {};

    auto load_ch = [&](int ch, int buf) {
        uint32_t ab = smem + buf*24576;
        uint32_t bb = ab + 8192;
        #pragma unroll
        for (int e = tid; e < 512; e += 256) {
            int row = e >> 3, c = e & 7;
            cp16(ab + row*128 + ((c*16) ^ ((row&7)<<4)), Wb + (size_t)row*(KP3*2) + ch*128 + c*16);
        }
        #pragma unroll
        for (int e = tid; e < 1024; e += 256) {
            int row = e >> 3, c = e & 7;
            cp16(bb + row*128 + ((c*16) ^ ((row&7)<<4)), Xb + (size_t)row*(KP3*2) + ch*128 + c*16);
        }
        CP_COMMIT();
    };

    load_ch(0, 0);
    for (int ch = 0; ch < 12; ch++) {
        if (ch + 1 < 12) { load_ch(ch + 1, (ch + 1) & 1); CP_WAIT1(); }
        else             { CP_WAIT0(); }
        __syncthreads();
        uint32_t ab = smem + (ch & 1)*24576;
        uint32_t bbuf = ab + 8192;
        #pragma unroll
        for (int kcl = 0; kcl < 2; kcl++) {
            int kc = wk*2 + kcl;
            uint32_t a0[4], a1[4];
            ldsm4(a0, ab + (wm*32 +      qo)*128 + (((kc*16 + qsel)*2) ^ aswz));
            ldsm4(a1, ab + (wm*32 + 16 + qo)*128 + (((kc*16 + qsel)*2) ^ aswz));
            #pragma unroll
            for (int p = 0; p < 4; p++) {
                uint32_t bb[4];
                ldsm4(bb, bbuf + (wn*64 + p*16 + jo)*128 + (((kc*16 + dsel)*2) ^ jswz));
                mma16816h(C0[2*p],   a0, bb[0], bb[1]);
                mma16816h(C0[2*p+1], a0, bb[2], bb[3]);
                mma16816h(C1[2*p],   a1, bb[0], bb[1]);
                mma16816h(C1[2*p+1], a1, bb[2], bb[3]);
            }
        }
        __syncthreads();
    }

    // K-reduce through Cs: wk=1 store, wk=0 add
    float (*Cs)[129] = (float(*)[129])sb;
    {
        int r = lane >> 2, cb = (lane & 3)*2;
        if (wk) {
            #pragma unroll
            for (int nt = 0; nt < 8; nt++)
                #pragma unroll
                for (int hf = 0; hf < 2; hf++) {
                    Cs[wm*32      + r + 8*hf][wn*64 + nt*8 + cb]     = C0[nt][2*hf];
                    Cs[wm*32      + r + 8*hf][wn*64 + nt*8 + cb + 1] = C0[nt][2*hf+1];
                    Cs[wm*32 + 16 + r + 8*hf][wn*64 + nt*8 + cb]     = C1[nt][2*hf];
                    Cs[wm*32 + 16 + r + 8*hf][wn*64 + nt*8 + cb + 1] = C1[nt][2*hf+1];
                }
        }
        __syncthreads();
        if (!wk) {
            #pragma unroll
            for (int nt = 0; nt < 8; nt++)
                #pragma unroll
                for (int hf = 0; hf < 2; hf++) {
                    Cs[wm*32      + r + 8*hf][wn*64 + nt*8 + cb]     += C0[nt][2*hf];
                    Cs[wm*32      + r + 8*hf][wn*64 + nt*8 + cb + 1] += C0[nt][2*hf+1];
                    Cs[wm*32 + 16 + r + 8*hf][wn*64 + nt*8 + cb]     += C1[nt][2*hf];
                    Cs[wm*32 + 16 + r + 8*hf][wn*64 + nt*8 + cb + 1] += C1[nt][2*hf+1];
                }
        }
    }
    __syncthreads();

    if (mat == 0) {
        int n = tid >> 1, dh = (tid & 1)*32;
        uint32_t pk[16];
        float s = 0.f;
        #pragma unroll
        for (int t = 0; t < 16; t++) {
            unsigned short h0 = hfb(Cs[dh + 2*t][n]);
            unsigned short h1 = hfb(Cs[dh + 2*t + 1][n]);
            float r0 = hff(h0), r1 = hff(h1);
            s += r0*r0 + r1*r1;
            pk[t] = (uint32_t)h0 | ((uint32_t)h1 << 16);
        }
        uint4* dst = (uint4*)((char*)g_kh + (((size_t)bh*NKP + n0 + n)*DHH + dh)*2);
        #pragma unroll
        for (int t = 0; t < 4; t++) dst[t] = ((uint4*)pk)[t];
        s += __shfl_xor_sync(0xffffffffu, s, 1);
        if (!(tid & 1)) g_k2[(size_t)bh*NKP + n0 + n] = s * C2F;
    } else {
        int d = tid >> 2, q = (tid & 3)*32;
        uint32_t ph[16];
        #pragma unroll
        for (int t = 0; t < 16; t++)
            ph[t] = (uint32_t)hfb(Cs[d][q + 2*t]) | ((uint32_t)hfb(Cs[d][q + 2*t + 1]) << 16);
        uint4* dh_ = (uint4*)((char*)g_vh + (((size_t)bh*DHH + d)*NKP + n0 + q)*2);
        #pragma unroll
        for (int t = 0; t < 4; t++) dh_[t] = ((uint4*)ph)[t];
    }
}

// ===================== fp16 mma attention (split-j, fused combine via semaphore) =====================
// grid (18 i-tiles, 16 bh, 2 j-halves). jh0: blocks [0,19); jh1: [19,37).
// 4 warps x 32 query rows; last-arriving CTA of each (i-tile,bh) pair combines inline.
#define SM_BUF0 16384
#define SM_K2A  32768
#define SM_TOT  33280

__global__ __launch_bounds__(128, 3) void attn_mma_kernel() {
    __shared__ __align__(1024) unsigned char sb[SM_TOT];
    __shared__ unsigned int s_last;
    const int tid  = threadIdx.x;
    const int lane = tid & 31;
    const int warp = tid >> 5;       // 0..3
    const int bh   = blockIdx.y;
    const int i0   = blockIdx.x * MT;
    const int jh   = blockIdx.z;
    const int blk0 = jh ? 19 : 0;
    const int blkE = jh ? NBLK : 19;
    const uint32_t smem = s2u(sb);

    // ---- Q tile into region0 (swizzled) ----
    {
        const uint4* src = (const uint4*)(g_kh + ((size_t)bh*NKP + i0)*DHH);
        #pragma unroll
        for (int e = tid; e < 1024; e += 128) {
            int row = e >> 3, ch = e & 7;
            *(uint4*)(sb + row*128 + ((ch*16) ^ ((row & 7) << 4))) = src[row*8 + ch];
        }
    }

    const char* kgb = (const char*)g_kh + (size_t)bh*NKP*DHH*2;
    const char* vgb = (const char*)g_vh + (size_t)bh*DHH*NKP*2;
    const float* k2g = g_k2 + (size_t)bh*NKP;

    auto load_blk = [&](int blk, int buf) {
        int j0 = blk * NJ;
        uint32_t kb = smem + (buf ? 0 : SM_BUF0);
        uint32_t vb = kb + 8192;
        #pragma unroll
        for (int e = tid; e < 512; e += 128) {
            int row = e >> 3, ch = e & 7;
            uint32_t so = row*128 + ((ch*16) ^ ((row & 7) << 4));
            cp16(kb + so, kgb + ((size_t)(j0 + row)*DHH)*2 + ch*16);
            cp16(vb + so, vgb + ((size_t)row*NKP + j0)*2 + ch*16);
        }
        if (tid < 16) cp16(smem + SM_K2A + buf*256 + tid*16, (const char*)(k2g + j0) + tid*16);
        CP_COMMIT();
    };

    load_blk(blk0, 0);       // into region1, Q untouched
    __syncthreads();

    // ---- Q fragments (resident): 2 row-groups of 16 ----
    uint32_t qa[4][2][4];
    {
        int qo = ((lane >> 3) & 1)*8 + (lane & 7);
        int qsel = ((lane >> 4) & 1)*8;
        int swz = (qo & 7) << 4;
        #pragma unroll
        for (int g = 0; g < 2; g++) {
            uint32_t rowbase = smem + (warp*32 + g*16 + qo)*128;
            #pragma unroll
            for (int kc = 0; kc < 4; kc++)
                ldsm4(qa[kc][g], rowbase + (((kc*16 + qsel)*2) ^ swz));
        }
    }
    __syncthreads();         // all warps done reading Q before buf1 writes begin

    const int r0g = i0 + warp*32 + (lane >> 2);
    const float q2_00 = k2g[r0g];
    const float q2_01 = k2g[r0g + 8];
    const float q2_10 = k2g[r0g + 16];
    const float q2_11 = k2g[r0g + 24];
    float O0[8][4] = {}, O1[8][4] = {};
    float Oden0[4] = {}, Oden1[4] = {};
    const uint32_t bone = (lane < 4) ? 0x3C003C00u : 0u;

    const int jo   = ((lane >> 4) & 1)*8 + (lane & 7);
    const int dsel = ((lane >> 3) & 1)*8;
    const int jswz = (jo & 7) << 4;

    for (int blk = blk0; blk < blkE; blk++) {
        const int j0 = blk * NJ;
        const int buf = (blk - blk0) & 1;
        if (blk + 1 < blkE) { load_blk(blk + 1, buf ^ 1); CP_WAIT1(); }
        else                { CP_WAIT0(); }
        __syncthreads();

        const uint32_t kb = smem + (buf ? 0 : SM_BUF0);
        const uint32_t vb = kb + 8192;
        const float* k2s = (const float*)(sb + SM_K2A + buf*256);
        const bool maskblk = (j0 == i0) | (j0 == i0 + 64);

        #pragma unroll
        for (int p = 0; p < 4; p++) {
            float Sa0[4] = {}, Sb0[4] = {}, Sa1[4] = {}, Sb1[4] = {};
            #pragma unroll
            for (int kc = 0; kc < 4; kc++) {
                uint32_t b[4];
                ldsm4(b, kb + (p*16 + jo)*128 + (((kc*16 + dsel)*2) ^ jswz));
                mma16816h(Sa0, qa[kc][0], b[0], b[1]);
                mma16816h(Sb0, qa[kc][0], b[2], b[3]);
                mma16816h(Sa1, qa[kc][1], b[0], b[1]);
                mma16816h(Sb1, qa[kc][1], b[2], b[3]);
            }

            uint32_t ap0[4], ap1[4];
            {
                int col0 = p*16 + (lane & 3)*2;
                float k2a = k2s[col0], k2b = k2s[col0 + 1];
                float k2c = k2s[col0 + 8], k2d = k2s[col0 + 9];
                {
                    float da = fmaxf(fmaf(Sa0[0], -TWO_C2F, q2_00 + k2a), 1e-12f);
                    float db = fmaxf(fmaf(Sa0[1], -TWO_C2F, q2_00 + k2b), 1e-12f);
                    ap0[0] = h2ex2(pack_h2(-fsqrt(da), -fsqrt(db)));
                    float dc = fmaxf(fmaf(Sa0[2], -TWO_C2F, q2_01 + k2a), 1e-12f);
                    float dd = fmaxf(fmaf(Sa0[3], -TWO_C2F, q2_01 + k2b), 1e-12f);
                    ap0[1] = h2ex2(pack_h2(-fsqrt(dc), -fsqrt(dd)));
                    float de = fmaxf(fmaf(Sb0[0], -TWO_C2F, q2_00 + k2c), 1e-12f);
                    float df = fmaxf(fmaf(Sb0[1], -TWO_C2F, q2_00 + k2d), 1e-12f);
                    ap0[2] = h2ex2(pack_h2(-fsqrt(de), -fsqrt(df)));
                    float dg = fmaxf(fmaf(Sb0[2], -TWO_C2F, q2_01 + k2c), 1e-12f);
                    float dh = fmaxf(fmaf(Sb0[3], -TWO_C2F, q2_01 + k2d), 1e-12f);
                    ap0[3] = h2ex2(pack_h2(-fsqrt(dg), -fsqrt(dh)));
                }
                {
                    float da = fmaxf(fmaf(Sa1[0], -TWO_C2F, q2_10 + k2a), 1e-12f);
                    float db = fmaxf(fmaf(Sa1[1], -TWO_C2F, q2_10 + k2b), 1e-12f);
                    ap1[0] = h2ex2(pack_h2(-fsqrt(da), -fsqrt(db)));
                    float dc = fmaxf(fmaf(Sa1[2], -TWO_C2F, q2_11 + k2a), 1e-12f);
                    float dd = fmaxf(fmaf(Sa1[3], -TWO_C2F, q2_11 + k2b), 1e-12f);
                    ap1[1] = h2ex2(pack_h2(-fsqrt(dc), -fsqrt(dd)));
                    float de = fmaxf(fmaf(Sb1[0], -TWO_C2F, q2_10 + k2c), 1e-12f);
                    float df = fmaxf(fmaf(Sb1[1], -TWO_C2F, q2_10 + k2d), 1e-12f);
                    ap1[2] = h2ex2(pack_h2(-fsqrt(de), -fsqrt(df)));
                    float dg = fmaxf(fmaf(Sb1[2], -TWO_C2F, q2_11 + k2c), 1e-12f);
                    float dh = fmaxf(fmaf(Sb1[3], -TWO_C2F, q2_11 + k2d), 1e-12f);
                    ap1[3] = h2ex2(pack_h2(-fsqrt(dg), -fsqrt(dh)));
                }

                if (maskblk) {
                    int jg = j0 + col0;
                    int jhh = jg + 8;
                    if (jg      == r0g)      ap0[0] &= 0xFFFF0000u;
                    if (jg + 1  == r0g)      ap0[0] &= 0x0000FFFFu;
                    if (jg      == r0g + 8)  ap0[1] &= 0xFFFF0000u;
                    if (jg + 1  == r0g + 8)  ap0[1] &= 0x0000FFFFu;
                    if (jhh     == r0g)      ap0[2] &= 0xFFFF0000u;
                    if (jhh + 1 == r0g)      ap0[2] &= 0x0000FFFFu;
                    if (jhh     == r0g + 8)  ap0[3] &= 0xFFFF0000u;
                    if (jhh + 1 == r0g + 8)  ap0[3] &= 0x0000FFFFu;
                    if (jg      == r0g + 16) ap1[0] &= 0xFFFF0000u;
                    if (jg + 1  == r0g + 16) ap1[0] &= 0x0000FFFFu;
                    if (jg      == r0g + 24) ap1[1] &= 0xFFFF0000u;
                    if (jg + 1  == r0g + 24) ap1[1] &= 0x0000FFFFu;
                    if (jhh     == r0g + 16) ap1[2] &= 0xFFFF0000u;
                    if (jhh + 1 == r0g + 16) ap1[2] &= 0x0000FFFFu;
                    if (jhh     == r0g + 24) ap1[3] &= 0xFFFF0000u;
                    if (jhh + 1 == r0g + 24) ap1[3] &= 0x0000FFFFu;
                }
            }

            #pragma unroll
            for (int dtp = 0; dtp < 4; dtp++) {
                uint32_t vh[4];
                ldsm4(vh, vb + (dtp*16 + jo)*128 + (((p*16 + dsel)*2) ^ jswz));
                mma16816h(O0[2*dtp],   ap0, vh[0], vh[1]);
                mma16816h(O0[2*dtp+1], ap0, vh[2], vh[3]);
                mma16816h(O1[2*dtp],   ap1, vh[0], vh[1]);
                mma16816h(O1[2*dtp+1], ap1, vh[2], vh[3]);
            }
            mma16816h(Oden0, ap0, bone, bone);
            mma16816h(Oden1, ap1, bone, bone);
        }
        __syncthreads();
    }

    // ---- write UNNORMALIZED partials (f32), both groups ----
    {
        float* ob = g_Opart + ((size_t)(jh*16 + bh)*DHH)*NN;
        #pragma unroll
        for (int dt = 0; dt < 8; dt++) {
            int d0 = dt*8 + (lane & 3)*2;
            ob[(size_t)d0*NN + r0g]            = O0[dt][0];
            ob[(size_t)(d0+1)*NN + r0g]        = O0[dt][1];
            ob[(size_t)d0*NN + r0g + 8]        = O0[dt][2];
            ob[(size_t)(d0+1)*NN + r0g + 8]    = O0[dt][3];
            ob[(size_t)d0*NN + r0g + 16]       = O1[dt][0];
            ob[(size_t)(d0+1)*NN + r0g + 16]   = O1[dt][1];
            ob[(size_t)d0*NN + r0g + 24]       = O1[dt][2];
            ob[(size_t)(d0+1)*NN + r0g + 24]   = O1[dt][3];
        }
        if ((lane & 3) == 0) {
            float* db = g_dpart + (size_t)(jh*16 + bh)*NN;
            db[r0g]      = Oden0[0];
            db[r0g + 8]  = Oden0[2];
            db[r0g + 16] = Oden1[0];
            db[r0g + 24] = Oden1[2];
        }
    }

    // ---- semaphore: last-arriving CTA of the (i-tile, bh) pair combines ----
    __threadfence();
    __syncthreads();
    if (tid == 0) s_last = atomicAdd(&g_flag[blockIdx.x*16 + bh], 1u);
    __syncthreads();
    if (s_last == 1) {
        int i = i0 + tid;    // 128 threads, one row each
        int bq = bh >> 3, hq = bh & 7;
        float den = g_dpart[(size_t)bh*NN + i] + g_dpart[(size_t)(16 + bh)*NN + i];
        float rin = 1.f / den;
        const float* o0 = g_Opart + (size_t)bh*DHH*NN + i;
        const float* o1 = g_Opart + (size_t)(16 + bh)*DHH*NN + i;
        char* pbase = (char*)g_attsp + ((size_t)(bq*NN + i))*(KO3*2) + 6*(hq*64);
        #pragma unroll
        for (int d = 0; d < DHH; d += 2) {
            float a = (o0[(size_t)d*NN]     + o1[(size_t)d*NN])     * rin;
            float b = (o0[(size_t)(d+1)*NN] + o1[(size_t)(d+1)*NN]) * rin;
            unsigned short h0 = hfb(a), h1 = hfb(b);
            uint32_t* p = (uint32_t*)(pbase + 6*d);
            p[0] = (uint32_t)h0 | ((uint32_t)h0 << 16);
            p[1] = (uint32_t)hfb(a - hff(h0)) | ((uint32_t)h1 << 16);
            p[2] = (uint32_t)h1 | ((uint32_t)hfb(b - hff(h1)) << 16);
        }
    }
}

// ===================== output projection GEMM (triple-fp16 mma, K-split warps) =====================
__global__ __launch_bounds__(256, 2) void out_mma_kernel(float* __restrict__ out) {
    __shared__ __align__(1024) unsigned char sb[49152];
    const int tid = threadIdx.x, lane = tid & 31, warp = tid >> 5;
    const int b = blockIdx.z;
    const int m0 = blockIdx.y * 64, n0 = blockIdx.x * 128;
    const uint32_t smem = s2u(sb);
    const char* Wb = (const char*)g_wo3 + (size_t)m0*(KO3*2);
    const char* Xb = (const char*)g_attsp + (size_t)(b*NN + n0)*(KO3*2);
    const int wn = warp & 1, wm = (warp >> 1) & 1, wk = warp >> 2;
    const int qo = ((lane>>3)&1)*8 + (lane&7), qsel = ((lane>>4)&1)*8, aswz = (qo&7)<<4;
    const int jo = ((lane>>4)&1)*8 + (lane&7), dsel = ((lane>>3)&1)*8, jswz = (jo&7)<<4;
    float C0[8][4] = {}, C1[8][4] = {};

    auto load_ch = [&](int ch, int buf) {
        uint32_t ab = smem + buf*24576;
        uint32_t bb = ab + 8192;
        #pragma unroll
        for (int e = tid; e < 512; e += 256) {
            int row = e >> 3, c = e & 7;
            cp16(ab + row*128 + ((c*16) ^ ((row&7)<<4)), Wb + (size_t)row*(KO3*2) + ch*128 + c*16);
        }
        #pragma unroll
        for (int e = tid; e < 1024; e += 256) {
            int row = e >> 3, c = e & 7;
            cp16(bb + row*128 + ((c*16) ^ ((row&7)<<4)), Xb + (size_t)row*(KO3*2) + ch*128 + c*16);
        }
        CP_COMMIT();
    };

    load_ch(0, 0);
    for (int ch = 0; ch < 24; ch++) {
        if (ch + 1 < 24) { load_ch(ch + 1, (ch + 1) & 1); CP_WAIT1(); }
        else             { CP_WAIT0(); }
        __syncthreads();
        uint32_t ab = smem + (ch & 1)*24576;
        uint32_t bbuf = ab + 8192;
        #pragma unroll
        for (int kcl = 0; kcl < 2; kcl++) {
            int kc = wk*2 + kcl;
            uint32_t a0[4], a1[4];
            ldsm4(a0, ab + (wm*32 +      qo)*128 + (((kc*16 + qsel)*2) ^ aswz));
            ldsm4(a1, ab + (wm*32 + 16 + qo)*128 + (((kc*16 + qsel)*2) ^ aswz));
            #pragma unroll
            for (int p = 0; p < 4; p++) {
                uint32_t bb[4];
                ldsm4(bb, bbuf + (wn*64 + p*16 + jo)*128 + (((kc*16 + dsel)*2) ^ jswz));
                mma16816h(C0[2*p],   a0, bb[0], bb[1]);
                mma16816h(C0[2*p+1], a0, bb[2], bb[3]);
                mma16816h(C1[2*p],   a1, bb[0], bb[1]);
                mma16816h(C1[2*p+1], a1, bb[2], bb[3]);
            }
        }
        __syncthreads();
    }

    // K-reduce: wk=1 stage to Cs, wk=0 add + write out
    float (*Cs)[129] = (float(*)[129])sb;
    int r = lane >> 2, cb = (lane & 3)*2;
    if (wk) {
        #pragma unroll
        for (int nt = 0; nt < 8; nt++)
            #pragma unroll
            for (int hf = 0; hf < 2; hf++) {
                Cs[wm*32      + r + 8*hf][wn*64 + nt*8 + cb]     = C0[nt][2*hf];
                Cs[wm*32      + r + 8*hf][wn*64 + nt*8 + cb + 1] = C0[nt][2*hf+1];
                Cs[wm*32 + 16 + r + 8*hf][wn*64 + nt*8 + cb]     = C1[nt][2*hf];
                Cs[wm*32 + 16 + r + 8*hf][wn*64 + nt*8 + cb + 1] = C1[nt][2*hf+1];
            }
    }
    __syncthreads();
    if (!wk) {
        #pragma unroll
        for (int nt = 0; nt < 8; nt++)
            #pragma unroll
            for (int hf = 0; hf < 2; hf++) {
                {
                    size_t o = (size_t)(b*CC + m0 + wm*32 + r + 8*hf)*NN + n0 + wn*64 + nt*8 + cb;
                    out[o]     = C0[nt][2*hf]   + Cs[wm*32 + r + 8*hf][wn*64 + nt*8 + cb];
                    out[o + 1] = C0[nt][2*hf+1] + Cs[wm*32 + r + 8*hf][wn*64 + nt*8 + cb + 1];
                }
                {
                    size_t o = (size_t)(b*CC + m0 + wm*32 + 16 + r + 8*hf)*NN + n0 + wn*64 + nt*8 + cb;
                    out[o]     = C1[nt][2*hf]   + Cs[wm*32 + 16 + r + 8*hf][wn*64 + nt*8 + cb];
                    out[o + 1] = C1[nt][2*hf+1] + Cs[wm*32 + 16 + r + 8*hf][wn*64 + nt*8 + cb + 1];
                }
            }
    }
}

extern "C" void kernel_launch(void* const* d_in, const int* in_sizes, int n_in,
                              void* d_out, int out_size) {
    const float* fmap    = (const float*)d_in[0];
    const float* gamma   = (const float*)d_in[1];
    const float* w_qk    = (const float*)d_in[2];
    const float* w_v     = (const float*)d_in[3];
    const float* null_kv = (const float*)d_in[4];
    const float* w_out   = (const float*)d_in[5];
    float* out = (float*)d_out;

    rms_fused_kernel<<<BB*72, 256>>>(fmap, gamma);
    prep_kernel<<<1792, 256>>>(w_qk, w_v, w_out, null_kv);
    proj_mma_kernel<<<dim3(18, 8, 4), 256>>>();
    attn_mma_kernel<<<dim3(NIT, BB*HH, 2), 128>>>();
    out_mma_kernel<<<dim3(18, 4, 2), 256>>>(out);
}

// round 17
// speedup vs baseline: 1.0151x; 1.0151x over previous
#include <cuda_runtime.h>
#include <cuda_fp16.h>
#include <cstdint>

#define BB  2
#define CC  256
#define NN  2304
#define HH  8
#define DHH 64
#define OO  512
#define NKP 2368          // 2304 tokens + null@2304 + 63 pad = 37*64
#define NJ  64
#define NBLK (NKP/NJ)     // 37
#define KP3 768           // 3*256
#define KO3 1536          // 3*512

#define C2F     0.0325213903f    // (0.125*log2e)^2
#define TWO_C2F 0.0650427806f

// ---- scratch (device globals; no allocation allowed) ----
__device__ __align__(16) __half g_normsp[BB*NN*KP3];   // B for proj: (xh,xh,xl) triples, n-major
__device__ __align__(16) __half g_wqk3[OO*KP3];        // A: (wh,wl,wh) triples
__device__ __align__(16) __half g_wv3[OO*KP3];
__device__ __align__(16) __half g_wo3[CC*KO3];
__device__ __align__(16) __half g_kh[BB*HH*NKP*DHH];   // keys fp16 (bh, n, d); null@2304
__device__ __align__(16) __half g_vh[BB*HH*DHH*NKP];   // V fp16 (bh, d, n)
__device__ float g_k2[BB*HH*NKP];                      // C2 * |k_n|^2 of ROUNDED keys; big on pads
__device__ __align__(16) __half g_attsp[BB*NN*KO3];    // B for out: (oh,oh,ol) triples

static __device__ __forceinline__ uint32_t s2u(const void* p){
    uint32_t a;
    asm("{ .reg .u64 t; cvta.to.shared.u64 t, %1; cvt.u32.u64 %0, t; }" : "=r"(a) : "l"(p));
    return a;
}
__device__ __forceinline__ void ldsm4(uint32_t* r, uint32_t addr){
    asm volatile("ldmatrix.sync.aligned.m8n8.x4.shared.b16 {%0,%1,%2,%3}, [%4];"
        : "=r"(r[0]), "=r"(r[1]), "=r"(r[2]), "=r"(r[3]) : "r"(addr));
}
__device__ __forceinline__ void mma16816h(float* c, const uint32_t* a, uint32_t b0, uint32_t b1){
    asm volatile("mma.sync.aligned.m16n8k16.row.col.f32.f16.f16.f32 "
        "{%0,%1,%2,%3}, {%4,%5,%6,%7}, {%8,%9}, {%0,%1,%2,%3};"
        : "+f"(c[0]), "+f"(c[1]), "+f"(c[2]), "+f"(c[3])
        : "r"(a[0]), "r"(a[1]), "r"(a[2]), "r"(a[3]), "r"(b0), "r"(b1));
}
__device__ __forceinline__ uint32_t pack_h2(float x, float y){
    __half2 t = __floats2half2_rn(x, y);
    return *reinterpret_cast<uint32_t*>(&t);
}
__device__ __forceinline__ uint32_t h2ex2(uint32_t x){
    uint32_t r; asm("ex2.approx.f16x2 %0, %1;" : "=r"(r) : "r"(x)); return r;
}
__device__ __forceinline__ float fsqrt(float x){
    float r; asm("sqrt.approx.f32 %0, %1;" : "=f"(r) : "f"(x)); return r;
}
__device__ __forceinline__ unsigned short hfb(float x){
    __half h = __float2half_rn(x);
    return *reinterpret_cast<unsigned short*>(&h);
}
__device__ __forceinline__ float hff(unsigned short u){
    __half h = *reinterpret_cast<__half*>(&u);
    return __half2float(h);
}
__device__ __forceinline__ void cp16(uint32_t d, const void* s){
    asm volatile("cp.async.cg.shared.global [%0], [%1], 16;" :: "r"(d), "l"(s));
}
#define CP_COMMIT() asm volatile("cp.async.commit_group;" ::: "memory")
#define CP_WAIT1()  asm volatile("cp.async.wait_group 1;" ::: "memory")
#define CP_WAIT0()  asm volatile("cp.async.wait_group 0;" ::: "memory")

// ===================== fused RMSNorm + split + transpose =====================
__global__ __launch_bounds__(256, 2) void rms_fused_kernel(const float* __restrict__ fmap,
                                                           const float* __restrict__ gamma) {
    __shared__ float ts[256][33];
    __shared__ float gs[256];
    __shared__ float part[8][32];
    __shared__ float sc[32];
    int b  = blockIdx.x / 72;
    int n0 = (blockIdx.x % 72) * 32;
    int tid = threadIdx.x;
    gs[tid] = gamma[tid];
    #pragma unroll
    for (int e = tid; e < 8192; e += 256) {
        int cc = e >> 5, nn = e & 31;
        ts[cc][nn] = fmap[((size_t)b*CC + cc)*NN + n0 + nn];
    }
    __syncthreads();
    {
        int w = tid >> 5, l = tid & 31;
        float s = 0.f;
        #pragma unroll
        for (int r = 0; r < 32; r++) { float v = ts[w*32 + r][l]; s += v*v; }
        part[w][l] = s;
    }
    __syncthreads();
    if (tid < 32) {
        float t = 0.f;
        #pragma unroll
        for (int i = 0; i < 8; i++) t += part[i][tid];
        sc[tid] = 16.0f / fmaxf(sqrtf(t), 1e-12f);
    }
    __syncthreads();
    int nn = tid >> 3, cseg = (tid & 7)*32;
    float scv = sc[nn];
    char* rowp = (char*)g_normsp + (size_t)(b*NN + n0 + nn)*(KP3*2) + 6*cseg;
    #pragma unroll
    for (int b8 = 0; b8 < 4; b8++) {
        uint32_t u[12];
        #pragma unroll
        for (int pr = 0; pr < 4; pr++) {
            int c = cseg + b8*8 + pr*2;
            float x0 = ts[c][nn]*scv*gs[c];
            float x1 = ts[c+1][nn]*scv*gs[c+1];
            unsigned short h0 = hfb(x0), l0 = hfb(x0 - hff(h0));
            unsigned short h1 = hfb(x1), l1 = hfb(x1 - hff(h1));
            u[pr*3+0] = (uint32_t)h0 | ((uint32_t)h0 << 16);
            u[pr*3+1] = (uint32_t)l0 | ((uint32_t)h1 << 16);
            u[pr*3+2] = (uint32_t)h1 | ((uint32_t)l1 << 16);
        }
        uint4* wp = (uint4*)(rowp + b8*48);
        wp[0] = ((uint4*)u)[0]; wp[1] = ((uint4*)u)[1]; wp[2] = ((uint4*)u)[2];
    }
}

// ===================== weight split + null/pad fill (merged) =====================
__global__ __launch_bounds__(256) void prep_kernel(const float* __restrict__ wqk,
                                                   const float* __restrict__ wv,
                                                   const float* __restrict__ wout,
                                                   const float* __restrict__ null_kv) {
    int bid = blockIdx.x;
    if (bid < 1536) {
        int idx = bid*256 + threadIdx.x;   // 393216
        float w;
        unsigned short* d;
        if (idx < 131072)      { w = wqk[idx];           d = (unsigned short*)g_wqk3 + 3*(size_t)idx; }
        else if (idx < 262144) { w = wv[idx - 131072];   d = (unsigned short*)g_wv3  + 3*(size_t)(idx - 131072); }
        else                   { w = wout[idx - 262144]; d = (unsigned short*)g_wo3  + 3*(size_t)(idx - 262144); }
        unsigned short h = hfb(w);
        unsigned short l = hfb(w - hff(h));
        d[0] = h; d[1] = l; d[2] = h;
    } else {
        int tid = (bid - 1536)*256 + threadIdx.x;   // 65536
        int slot  = tid & 63;
        int rowid = tid >> 6;        // bh*64 + d
        int d  = rowid & 63;
        int bh = rowid >> 6;
        int h  = bh & 7;
        if (slot == 0) {
            float kv = null_kv[h*DHH + d];
            float vv = null_kv[HH*DHH + h*DHH + d];
            ((unsigned short*)g_kh)[((size_t)bh*NKP + NN)*DHH + d] = hfb(kv);
            ((unsigned short*)g_vh)[((size_t)bh*DHH + d)*NKP + NN] = hfb(vv);
            if (d == 0) {
                float s = 0.f;
                #pragma unroll
                for (int t = 0; t < 64; t++) { float x = hff(hfb(null_kv[h*DHH + t])); s += x*x; }
                g_k2[(size_t)bh*NKP + NN] = s * C2F;
            }
        } else {
            int n = NN + slot;   // 2305..2367 pads
            ((unsigned short*)g_kh)[((size_t)bh*NKP + n)*DHH + d] = 0;
            ((unsigned short*)g_vh)[((size_t)bh*DHH + d)*NKP + n] = 0;
            if (d == 0) g_k2[(size_t)bh*NKP + n] = 1e9f;
        }
    }
}

// ===================== projection GEMM (triple-fp16 mma, K-split warps, 32-row tiles) =====================
__global__ __launch_bounds__(256, 2) void proj_mma_kernel() {
    __shared__ __align__(1024) unsigned char sb[49152];
    const int tid = threadIdx.x, lane = tid & 31, warp = tid >> 5;
    const int b = blockIdx.z >> 1, mat = blockIdx.z & 1;
    const int h = blockIdx.y, n0 = blockIdx.x * 128;
    const int bh = b*HH + h;
    const uint32_t smem = s2u(sb);
    const char* Wb = (const char*)(mat ? g_wv3 : g_wqk3) + (size_t)h*64*(KP3*2);
    const char* Xb = (const char*)g_normsp + (size_t)(b*NN + n0)*(KP3*2);
    const int wn = warp & 1, wm = (warp >> 1) & 1, wk = warp >> 2;
    const int qo = ((lane>>3)&1)*8 + (lane&7), qsel = ((lane>>4)&1)*8, aswz = (qo&7)<<4;
    const int jo = ((lane>>4)&1)*8 + (lane&7), dsel = ((lane>>3)&1)*8, jswz = (jo&7)<<4;
    float C0[8][4] = {}, C1[8][4] = {};

    auto load_ch = [&](int ch, int buf) {
        uint32_t ab = smem + buf*24576;
        uint32_t bb = ab + 8192;
        #pragma unroll
        for (int e = tid; e < 512; e += 256) {
            int row = e >> 3, c = e & 7;
            cp16(ab + row*128 + ((c*16) ^ ((row&7)<<4)), Wb + (size_t)row*(KP3*2) + ch*128 + c*16);
        }
        #pragma unroll
        for (int e = tid; e < 1024; e += 256) {
            int row = e >> 3, c = e & 7;
            cp16(bb + row*128 + ((c*16) ^ ((row&7)<<4)), Xb + (size_t)row*(KP3*2) + ch*128 + c*16);
        }
        CP_COMMIT();
    };

    load_ch(0, 0);
    for (int ch = 0; ch < 12; ch++) {
        if (ch + 1 < 12) { load_ch(ch + 1, (ch + 1) & 1); CP_WAIT1(); }
        else             { CP_WAIT0(); }
        __syncthreads();
        uint32_t ab = smem + (ch & 1)*24576;
        uint32_t bbuf = ab + 8192;
        #pragma unroll
        for (int kcl = 0; kcl < 2; kcl++) {
            int kc = wk*2 + kcl;
            uint32_t a0[4], a1[4];
            ldsm4(a0, ab + (wm*32 +      qo)*128 + (((kc*16 + qsel)*2) ^ aswz));
            ldsm4(a1, ab + (wm*32 + 16 + qo)*128 + (((kc*16 + qsel)*2) ^ aswz));
            #pragma unroll
            for (int p = 0; p < 4; p++) {
                uint32_t bb[4];
                ldsm4(bb, bbuf + (wn*64 + p*16 + jo)*128 + (((kc*16 + dsel)*2) ^ jswz));
                mma16816h(C0[2*p],   a0, bb[0], bb[1]);
                mma16816h(C0[2*p+1], a0, bb[2], bb[3]);
                mma16816h(C1[2*p],   a1, bb[0], bb[1]);
                mma16816h(C1[2*p+1], a1, bb[2], bb[3]);
            }
        }
        __syncthreads();
    }

    // K-reduce through Cs: wk=1 store, wk=0 add
    float (*Cs)[129] = (float(*)[129])sb;
    {
        int r = lane >> 2, cb = (lane & 3)*2;
        if (wk) {
            #pragma unroll
            for (int nt = 0; nt < 8; nt++)
                #pragma unroll
                for (int hf = 0; hf < 2; hf++) {
                    Cs[wm*32      + r + 8*hf][wn*64 + nt*8 + cb]     = C0[nt][2*hf];
                    Cs[wm*32      + r + 8*hf][wn*64 + nt*8 + cb + 1] = C0[nt][2*hf+1];
                    Cs[wm*32 + 16 + r + 8*hf][wn*64 + nt*8 + cb]     = C1[nt][2*hf];
                    Cs[wm*32 + 16 + r + 8*hf][wn*64 + nt*8 + cb + 1] = C1[nt][2*hf+1];
                }
        }
        __syncthreads();
        if (!wk) {
            #pragma unroll
            for (int nt = 0; nt < 8; nt++)
                #pragma unroll
                for (int hf = 0; hf < 2; hf++) {
                    Cs[wm*32      + r + 8*hf][wn*64 + nt*8 + cb]     += C0[nt][2*hf];
                    Cs[wm*32      + r + 8*hf][wn*64 + nt*8 + cb + 1] += C0[nt][2*hf+1];
                    Cs[wm*32 + 16 + r + 8*hf][wn*64 + nt*8 + cb]     += C1[nt][2*hf];
                    Cs[wm*32 + 16 + r + 8*hf][wn*64 + nt*8 + cb + 1] += C1[nt][2*hf+1];
                }
        }
    }
    __syncthreads();

    if (mat == 0) {
        int n = tid >> 1, dh = (tid & 1)*32;
        uint32_t pk[16];
        float s = 0.f;
        #pragma unroll
        for (int t = 0; t < 16; t++) {
            unsigned short h0 = hfb(Cs[dh + 2*t][n]);
            unsigned short h1 = hfb(Cs[dh + 2*t + 1][n]);
            float r0 = hff(h0), r1 = hff(h1);
            s += r0*r0 + r1*r1;
            pk[t] = (uint32_t)h0 | ((uint32_t)h1 << 16);
        }
        uint4* dst = (uint4*)((char*)g_kh + (((size_t)bh*NKP + n0 + n)*DHH + dh)*2);
        #pragma unroll
        for (int t = 0; t < 4; t++) dst[t] = ((uint4*)pk)[t];
        s += __shfl_xor_sync(0xffffffffu, s, 1);
        if (!(tid & 1)) g_k2[(size_t)bh*NKP + n0 + n] = s * C2F;
    } else {
        int d = tid >> 2, q = (tid & 3)*32;
        uint32_t ph[16];
        #pragma unroll
        for (int t = 0; t < 16; t++)
            ph[t] = (uint32_t)hfb(Cs[d][q + 2*t]) | ((uint32_t)hfb(Cs[d][q + 2*t + 1]) << 16);
        uint4* dh_ = (uint4*)((char*)g_vh + (((size_t)bh*DHH + d)*NKP + n0 + q)*2);
        #pragma unroll
        for (int t = 0; t < 4; t++) dh_[t] = ((uint4*)ph)[t];
    }
}

// ===================== fp16 mma attention (MT=64, 64 threads, 2 warps x 32 rows) =====================
// grid (36 i-tiles, 16 bh). Each CTA: all 37 j-blocks, direct normalized epilogue.
// smem: Q 8KB @0, buf0 @8192 (K 8KB + V 8KB), buf1 @24576, k2 2x256B @40960
#define SMA_B0 8192
#define SMA_K2 40960
#define SMA_TOT 41472

__global__ __launch_bounds__(64, 5) void attn_mma_kernel() {
    __shared__ __align__(1024) unsigned char sb[SMA_TOT];
    const int tid  = threadIdx.x;
    const int lane = tid & 31;
    const int warp = tid >> 5;       // 0..1
    const int bh   = blockIdx.y;
    const int i0   = blockIdx.x * 64;
    const uint32_t smem = s2u(sb);

    // ---- Q tile: 64 rows x 128B, swizzled ----
    {
        const uint4* src = (const uint4*)(g_kh + ((size_t)bh*NKP + i0)*DHH);
        #pragma unroll
        for (int e = tid; e < 512; e += 64) {
            int row = e >> 3, ch = e & 7;
            *(uint4*)(sb + row*128 + ((ch*16) ^ ((row & 7) << 4))) = src[row*8 + ch];
        }
    }

    const char* kgb = (const char*)g_kh + (size_t)bh*NKP*DHH*2;
    const char* vgb = (const char*)g_vh + (size_t)bh*DHH*NKP*2;
    const float* k2g = g_k2 + (size_t)bh*NKP;

    auto load_blk = [&](int blk, int buf) {
        int j0 = blk * NJ;
        uint32_t kb = smem + SMA_B0 + buf*16384;
        uint32_t vb = kb + 8192;
        #pragma unroll
        for (int e = tid; e < 512; e += 64) {
            int row = e >> 3, ch = e & 7;
            uint32_t so = row*128 + ((ch*16) ^ ((row & 7) << 4));
            cp16(kb + so, kgb + ((size_t)(j0 + row)*DHH)*2 + ch*16);
            cp16(vb + so, vgb + ((size_t)row*NKP + j0)*2 + ch*16);
        }
        if (tid < 16) cp16(smem + SMA_K2 + buf*256 + tid*16, (const char*)(k2g + j0) + tid*16);
        CP_COMMIT();
    };

    load_blk(0, 0);
    __syncthreads();      // Q stores + first buf issue ordered

    // ---- Q fragments (resident): 2 row-groups of 16 ----
    uint32_t qa[4][2][4];
    {
        int qo = ((lane >> 3) & 1)*8 + (lane & 7);
        int qsel = ((lane >> 4) & 1)*8;
        int swz = (qo & 7) << 4;
        #pragma unroll
        for (int g = 0; g < 2; g++) {
            uint32_t rowbase = smem + (warp*32 + g*16 + qo)*128;
            #pragma unroll
            for (int kc = 0; kc < 4; kc++)
                ldsm4(qa[kc][g], rowbase + (((kc*16 + qsel)*2) ^ swz));
        }
    }

    const int r0g = i0 + warp*32 + (lane >> 2);   // rows: r0g, +8 (grp0); +16, +24 (grp1)
    const float q2_00 = k2g[r0g];
    const float q2_01 = k2g[r0g + 8];
    const float q2_10 = k2g[r0g + 16];
    const float q2_11 = k2g[r0g + 24];
    float O0[8][4] = {}, O1[8][4] = {};
    float Oden0[4] = {}, Oden1[4] = {};
    const uint32_t bone = (lane < 4) ? 0x3C003C00u : 0u;

    const int jo   = ((lane >> 4) & 1)*8 + (lane & 7);
    const int dsel = ((lane >> 3) & 1)*8;
    const int jswz = (jo & 7) << 4;

    for (int blk = 0; blk < NBLK; blk++) {
        const int j0 = blk * NJ;
        const int buf = blk & 1;
        if (blk + 1 < NBLK) { load_blk(blk + 1, buf ^ 1); CP_WAIT1(); }
        else                { CP_WAIT0(); }
        __syncthreads();

        const uint32_t kb = smem + SMA_B0 + buf*16384;
        const uint32_t vb = kb + 8192;
        const float* k2s = (const float*)(sb + SMA_K2 + buf*256);
        const bool maskblk = (j0 == i0);

        #pragma unroll
        for (int p = 0; p < 4; p++) {
            float Sa0[4] = {}, Sb0[4] = {}, Sa1[4] = {}, Sb1[4] = {};
            #pragma unroll
            for (int kc = 0; kc < 4; kc++) {
                uint32_t b[4];
                ldsm4(b, kb + (p*16 + jo)*128 + (((kc*16 + dsel)*2) ^ jswz));
                mma16816h(Sa0, qa[kc][0], b[0], b[1]);
                mma16816h(Sb0, qa[kc][0], b[2], b[3]);
                mma16816h(Sa1, qa[kc][1], b[0], b[1]);
                mma16816h(Sb1, qa[kc][1], b[2], b[3]);
            }

            uint32_t ap0[4], ap1[4];
            {
                int col0 = p*16 + (lane & 3)*2;
                float k2a = k2s[col0], k2b = k2s[col0 + 1];
                float k2c = k2s[col0 + 8], k2d = k2s[col0 + 9];
                {
                    float da = fmaxf(fmaf(Sa0[0], -TWO_C2F, q2_00 + k2a), 1e-12f);
                    float db = fmaxf(fmaf(Sa0[1], -TWO_C2F, q2_00 + k2b), 1e-12f);
                    ap0[0] = h2ex2(pack_h2(-fsqrt(da), -fsqrt(db)));
                    float dc = fmaxf(fmaf(Sa0[2], -TWO_C2F, q2_01 + k2a), 1e-12f);
                    float dd = fmaxf(fmaf(Sa0[3], -TWO_C2F, q2_01 + k2b), 1e-12f);
                    ap0[1] = h2ex2(pack_h2(-fsqrt(dc), -fsqrt(dd)));
                    float de = fmaxf(fmaf(Sb0[0], -TWO_C2F, q2_00 + k2c), 1e-12f);
                    float df = fmaxf(fmaf(Sb0[1], -TWO_C2F, q2_00 + k2d), 1e-12f);
                    ap0[2] = h2ex2(pack_h2(-fsqrt(de), -fsqrt(df)));
                    float dg = fmaxf(fmaf(Sb0[2], -TWO_C2F, q2_01 + k2c), 1e-12f);
                    float dh = fmaxf(fmaf(Sb0[3], -TWO_C2F, q2_01 + k2d), 1e-12f);
                    ap0[3] = h2ex2(pack_h2(-fsqrt(dg), -fsqrt(dh)));
                }
                {
                    float da = fmaxf(fmaf(Sa1[0], -TWO_C2F, q2_10 + k2a), 1e-12f);
                    float db = fmaxf(fmaf(Sa1[1], -TWO_C2F, q2_10 + k2b), 1e-12f);
                    ap1[0] = h2ex2(pack_h2(-fsqrt(da), -fsqrt(db)));
                    float dc = fmaxf(fmaf(Sa1[2], -TWO_C2F, q2_11 + k2a), 1e-12f);
                    float dd = fmaxf(fmaf(Sa1[3], -TWO_C2F, q2_11 + k2b), 1e-12f);
                    ap1[1] = h2ex2(pack_h2(-fsqrt(dc), -fsqrt(dd)));
                    float de = fmaxf(fmaf(Sb1[0], -TWO_C2F, q2_10 + k2c), 1e-12f);
                    float df = fmaxf(fmaf(Sb1[1], -TWO_C2F, q2_10 + k2d), 1e-12f);
                    ap1[2] = h2ex2(pack_h2(-fsqrt(de), -fsqrt(df)));
                    float dg = fmaxf(fmaf(Sb1[2], -TWO_C2F, q2_11 + k2c), 1e-12f);
                    float dh = fmaxf(fmaf(Sb1[3], -TWO_C2F, q2_11 + k2d), 1e-12f);
                    ap1[3] = h2ex2(pack_h2(-fsqrt(dg), -fsqrt(dh)));
                }

                if (maskblk) {
                    int jg = j0 + col0;
                    int jhh = jg + 8;
                    if (jg      == r0g)      ap0[0] &= 0xFFFF0000u;
                    if (jg + 1  == r0g)      ap0[0] &= 0x0000FFFFu;
                    if (jg      == r0g + 8)  ap0[1] &= 0xFFFF0000u;
                    if (jg + 1  == r0g + 8)  ap0[1] &= 0x0000FFFFu;
                    if (jhh     == r0g)      ap0[2] &= 0xFFFF0000u;
                    if (jhh + 1 == r0g)      ap0[2] &= 0x0000FFFFu;
                    if (jhh     == r0g + 8)  ap0[3] &= 0xFFFF0000u;
                    if (jhh + 1 == r0g + 8)  ap0[3] &= 0x0000FFFFu;
                    if (jg      == r0g + 16) ap1[0] &= 0xFFFF0000u;
                    if (jg + 1  == r0g + 16) ap1[0] &= 0x0000FFFFu;
                    if (jg      == r0g + 24) ap1[1] &= 0xFFFF0000u;
                    if (jg + 1  == r0g + 24) ap1[1] &= 0x0000FFFFu;
                    if (jhh     == r0g + 16) ap1[2] &= 0xFFFF0000u;
                    if (jhh + 1 == r0g + 16) ap1[2] &= 0x0000FFFFu;
                    if (jhh     == r0g + 24) ap1[3] &= 0xFFFF0000u;
                    if (jhh + 1 == r0g + 24) ap1[3] &= 0x0000FFFFu;
                }
            }

            #pragma unroll
            for (int dtp = 0; dtp < 4; dtp++) {
                uint32_t vh[4];
                ldsm4(vh, vb + (dtp*16 + jo)*128 + (((p*16 + dsel)*2) ^ jswz));
                mma16816h(O0[2*dtp],   ap0, vh[0], vh[1]);
                mma16816h(O0[2*dtp+1], ap0, vh[2], vh[3]);
                mma16816h(O1[2*dtp],   ap1, vh[0], vh[1]);
                mma16816h(O1[2*dtp+1], ap1, vh[2], vh[3]);
            }
            mma16816h(Oden0, ap0, bone, bone);
            mma16816h(Oden1, ap1, bone, bone);
        }
        __syncthreads();
    }

    // ---- normalize + write attsp triples (oh, oh, ol) ----
    float rin00 = 1.f / __shfl_sync(0xffffffffu, Oden0[0], lane & 28);
    float rin01 = 1.f / __shfl_sync(0xffffffffu, Oden0[2], lane & 28);
    float rin10 = 1.f / __shfl_sync(0xffffffffu, Oden1[0], lane & 28);
    float rin11 = 1.f / __shfl_sync(0xffffffffu, Oden1[2], lane & 28);
    {
        int bq = bh >> 3, hq = bh & 7;
        char* abase = (char*)g_attsp + (size_t)bq*NN*(KO3*2);
        #pragma unroll
        for (int dt = 0; dt < 8; dt++) {
            int d0 = dt*8 + (lane & 3)*2;
            int k0 = hq*64 + d0;
            #pragma unroll
            for (int gg = 0; gg < 4; gg++) {
                int row = r0g + gg*8;
                float rin = (gg == 0) ? rin00 : (gg == 1) ? rin01 : (gg == 2) ? rin10 : rin11;
                float o0 = ((gg < 2) ? O0[dt][(gg&1)*2]     : O1[dt][(gg&1)*2])     * rin;
                float o1 = ((gg < 2) ? O0[dt][(gg&1)*2 + 1] : O1[dt][(gg&1)*2 + 1]) * rin;
                unsigned short h0 = hfb(o0), h1 = hfb(o1);
                uint32_t* p = (uint32_t*)(abase + (size_t)row*(KO3*2) + 6*k0);
                p[0] = (uint32_t)h0 | ((uint32_t)h0 << 16);
                p[1] = (uint32_t)hfb(o0 - hff(h0)) | ((uint32_t)h1 << 16);
                p[2] = (uint32_t)h1 | ((uint32_t)hfb(o1 - hff(h1)) << 16);
            }
        }
    }
}

// ===================== output projection GEMM (triple-fp16 mma, K-split warps) =====================
__global__ __launch_bounds__(256, 2) void out_mma_kernel(float* __restrict__ out) {
    __shared__ __align__(1024) unsigned char sb[49152];
    const int tid = threadIdx.x, lane = tid & 31, warp = tid >> 5;
    const int b = blockIdx.z;
    const int m0 = blockIdx.y * 64, n0 = blockIdx.x * 128;
    const uint32_t smem = s2u(sb);
    const char* Wb = (const char*)g_wo3 + (size_t)m0*(KO3*2);
    const char* Xb = (const char*)g_attsp + (size_t)(b*NN + n0)*(KO3*2);
    const int wn = warp & 1, wm = (warp >> 1) & 1, wk = warp >> 2;
    const int qo = ((lane>>3)&1)*8 + (lane&7), qsel = ((lane>>4)&1)*8, aswz = (qo&7)<<4;
    const int jo = ((lane>>4)&1)*8 + (lane&7), dsel = ((lane>>3)&1)*8, jswz = (jo&7)<<4;
    float C0[8][4] = {}, C1[8][4] = {};

    auto load_ch = [&](int ch, int buf) {
        uint32_t ab = smem + buf*24576;
        uint32_t bb = ab + 8192;
        #pragma unroll
        for (int e = tid; e < 512; e += 256) {
            int row = e >> 3, c = e & 7;
            cp16(ab + row*128 + ((c*16) ^ ((row&7)<<4)), Wb + (size_t)row*(KO3*2) + ch*128 + c*16);
        }
        #pragma unroll
        for (int e = tid; e < 1024; e += 256) {
            int row = e >> 3, c = e & 7;
            cp16(bb + row*128 + ((c*16) ^ ((row&7)<<4)), Xb + (size_t)row*(KO3*2) + ch*128 + c*16);
        }
        CP_COMMIT();
    };

    load_ch(0, 0);
    for (int ch = 0; ch < 24; ch++) {
        if (ch + 1 < 24) { load_ch(ch + 1, (ch + 1) & 1); CP_WAIT1(); }
        else             { CP_WAIT0(); }
        __syncthreads();
        uint32_t ab = smem + (ch & 1)*24576;
        uint32_t bbuf = ab + 8192;
        #pragma unroll
        for (int kcl = 0; kcl < 2; kcl++) {
            int kc = wk*2 + kcl;
            uint32_t a0[4], a1[4];
            ldsm4(a0, ab + (wm*32 +      qo)*128 + (((kc*16 + qsel)*2) ^ aswz));
            ldsm4(a1, ab + (wm*32 + 16 + qo)*128 + (((kc*16 + qsel)*2) ^ aswz));
            #pragma unroll
            for (int p = 0; p < 4; p++) {
                uint32_t bb[4];
                ldsm4(bb, bbuf + (wn*64 + p*16 + jo)*128 + (((kc*16 + dsel)*2) ^ jswz));
                mma16816h(C0[2*p],   a0, bb[0], bb[1]);
                mma16816h(C0[2*p+1], a0, bb[2], bb[3]);
                mma16816h(C1[2*p],   a1, bb[0], bb[1]);
                mma16816h(C1[2*p+1], a1, bb[2], bb[3]);
            }
        }
        __syncthreads();
    }

    // K-reduce: wk=1 stage to Cs, wk=0 add + write out
    float (*Cs)[129] = (float(*)[129])sb;
    int r = lane >> 2, cb = (lane & 3)*2;
    if (wk) {
        #pragma unroll
        for (int nt = 0; nt < 8; nt++)
            #pragma unroll
            for (int hf = 0; hf < 2; hf++) {
                Cs[wm*32      + r + 8*hf][wn*64 + nt*8 + cb]     = C0[nt][2*hf];
                Cs[wm*32      + r + 8*hf][wn*64 + nt*8 + cb + 1] = C0[nt][2*hf+1];
                Cs[wm*32 + 16 + r + 8*hf][wn*64 + nt*8 + cb]     = C1[nt][2*hf];
                Cs[wm*32 + 16 + r + 8*hf][wn*64 + nt*8 + cb + 1] = C1[nt][2*hf+1];
            }
    }
    __syncthreads();
    if (!wk) {
        #pragma unroll
        for (int nt = 0; nt < 8; nt++)
            #pragma unroll
            for (int hf = 0; hf < 2; hf++) {
                {
                    size_t o = (size_t)(b*CC + m0 + wm*32 + r + 8*hf)*NN + n0 + wn*64 + nt*8 + cb;
                    out[o]     = C0[nt][2*hf]   + Cs[wm*32 + r + 8*hf][wn*64 + nt*8 + cb];
                    out[o + 1] = C0[nt][2*hf+1] + Cs[wm*32 + r + 8*hf][wn*64 + nt*8 + cb + 1];
                }
                {
                    size_t o = (size_t)(b*CC + m0 + wm*32 + 16 + r + 8*hf)*NN + n0 + wn*64 + nt*8 + cb;
                    out[o]     = C1[nt][2*hf]   + Cs[wm*32 + 16 + r + 8*hf][wn*64 + nt*8 + cb];
                    out[o + 1] = C1[nt][2*hf+1] + Cs[wm*32 + 16 + r + 8*hf][wn*64 + nt*8 + cb + 1];
                }
            }
    }
}

extern "C" void kernel_launch(void* const* d_in, const int* in_sizes, int n_in,
                              void* d_out, int out_size) {
    const float* fmap    = (const float*)d_in[0];
    const float* gamma   = (const float*)d_in[1];
    const float* w_qk    = (const float*)d_in[2];
    const float* w_v     = (const float*)d_in[3];
    const float* null_kv = (const float*)d_in[4];
    const float* w_out   = (const float*)d_in[5];
    float* out = (float*)d_out;

    rms_fused_kernel<<<BB*72, 256>>>(fmap, gamma);
    prep_kernel<<<1792, 256>>>(w_qk, w_v, w_out, null_kv);
    proj_mma_kernel<<<dim3(18, 8, 4), 256>>>();
    attn_mma_kernel<<<dim3(36, BB*HH), 64>>>();
    out_mma_kernel<<<dim3(18, 4, 2), 256>>>(out);
}